// round 10
// baseline (speedup 1.0000x reference)
#include <cuda_runtime.h>
#include <cstdint>

typedef unsigned long long ull;

#define N_OBJ   4096
#define OBJ_DIM 1024
#define N_PAIRS 65536

// Scratch (device globals: no allocation allowed). 16B-aligned for float4 access.
// g_M layout: [c16][k], c16 in 0..15. c16<8: M[c][k] (sub half, k<1024 of W1 cols),
//             c16>=8: M[c-8][1024+k] (obj half).
__device__ __align__(16) float g_M[16 * 1024];   // 64 KB, ZERO before kernel A (atomics).
__device__ __align__(16) float g_cvec[8];        // W2@b1 + b2
__device__ __align__(16) float g_P[N_OBJ * 16];  // per-object projections (obj half + cvec)
__device__ int g_fmt;                            // 1 = pairs stored as int32, 0 = int64

// ---------------------------------------------------------------------------
// packed f32x2 helpers (Blackwell FFMA2 path)
// ---------------------------------------------------------------------------
__device__ __forceinline__ ull ffma2(ull a, ull b, ull c) {
    ull d;
    asm("fma.rn.f32x2 %0, %1, %2, %3;" : "=l"(d) : "l"(a), "l"(b), "l"(c));
    return d;
}
__device__ __forceinline__ ull pk2(float lo, float hi) {
    ull r;
    asm("mov.b64 %0, {%1, %2};" : "=l"(r) : "f"(lo), "f"(hi));
    return r;
}

// ---------------------------------------------------------------------------
// kDetect: decide pairs dtype. Read only the first 131072 int32 words (valid
// under BOTH hypotheses: int32 buffer = 131072 ints; int64 buffer = 262144).
// Under int64, odd words are high halves of indices < 4096 -> all zero.
// Under int32, odd words are 65536 random obj indices -> OR is nonzero.
// Deterministic: pure function of the input buffer.
// ---------------------------------------------------------------------------
__global__ __launch_bounds__(256) void kDetect(const int* __restrict__ pairs_i32) {
    __shared__ int s_or;
    if (threadIdx.x == 0) s_or = 0;
    __syncthreads();
    int v = 0;
    for (int i = threadIdx.x * 2 + 1; i < 131072; i += 512)
        v |= pairs_i32[i];
    #pragma unroll
    for (int o = 16; o; o >>= 1) v |= __shfl_xor_sync(0xffffffffu, v, o);
    if ((threadIdx.x & 31) == 0) atomicOr(&s_or, v);
    __syncthreads();
    if (threadIdx.x == 0) g_fmt = (s_or != 0) ? 1 : 0;
}

// ---------------------------------------------------------------------------
// Kernel A: g_M[c16][k] += partial of (W2 @ W1);  block 256 computes cvec.
// Grid: 257 blocks x 256 threads.
//   blocks 0..255: (kt = b & 63) k-tile of 32 columns, (jt = b >> 6) j-tile of 256.
// ---------------------------------------------------------------------------
__global__ __launch_bounds__(256) void kA(const float* __restrict__ W1,
                                          const float* __restrict__ W2,
                                          const float* __restrict__ b1,
                                          const float* __restrict__ b2) {
    __shared__ float sm[2048];   // phase1: W2 slice [8][256]; phase2: jy-reduction
    const int tid = threadIdx.x;

    if (blockIdx.x == 256) {     // cvec block
        int c = tid >> 5, lane = tid & 31;
        float s = 0.f;
        for (int j = lane; j < OBJ_DIM; j += 32)
            s += W2[c * OBJ_DIM + j] * b1[j];
        #pragma unroll
        for (int o = 16; o; o >>= 1) s += __shfl_xor_sync(0xffffffffu, s, o);
        if (lane == 0) g_cvec[c] = s + b2[c];
        return;
    }

    const int kt = blockIdx.x & 63;
    const int jt = blockIdx.x >> 6;    // 0..3
    const int kx = tid & 31;           // lane -> consecutive k (coalesced W1 reads)
    const int jy = tid >> 5;           // 0..7, constant per warp
    const int kk = kt * 32 + kx;       // 0..2047
    const int jb = jt * 256;

    // stage W2[c][jb..jb+256)
    for (int i = tid; i < 2048; i += 256)
        sm[i] = W2[(i >> 8) * OBJ_DIM + jb + (i & 255)];
    __syncthreads();

    float acc[8] = {0.f, 0.f, 0.f, 0.f, 0.f, 0.f, 0.f, 0.f};

    #pragma unroll
    for (int i = 0; i < 8; ++i) {
        float w[4];
        #pragma unroll
        for (int u = 0; u < 4; ++u) {               // batch loads for MLP
            int j = jy + 8 * (4 * i + u);           // local j in [0,256)
            w[u] = W1[(jb + j) * 2048 + kk];
        }
        #pragma unroll
        for (int u = 0; u < 4; ++u) {
            int j = jy + 8 * (4 * i + u);
            #pragma unroll
            for (int c = 0; c < 8; ++c)
                acc[c] += sm[c * 256 + j] * w[u];   // smem broadcast (j uniform/warp)
        }
    }

    __syncthreads();   // all warps done with W2 slice; reuse sm as reduction scratch
    #pragma unroll
    for (int c = 0; c < 8; ++c)
        sm[jy * 256 + kx * 8 + c] = acc[c];
    __syncthreads();

    // reduce over the 8 jy groups, then one atomicAdd per (k, c)
    {
        int kx2 = tid >> 3, c = tid & 7;
        float s = 0.f;
        #pragma unroll
        for (int q = 0; q < 8; ++q) s += sm[q * 256 + kx2 * 8 + c];
        int kk2 = kt * 32 + kx2;
        int c16 = ((kk2 >> 10) << 3) + c;
        atomicAdd(&g_M[c16 * 1024 + (kk2 & 1023)], s);
    }
}

// ---------------------------------------------------------------------------
// Kernel B: P[row][c16] = obj_feats[row] . Ms[c16]   (+ cvec on obj half)
// Grid: 128 blocks x 256 threads (8 warps). Warp owns 4 rows; lane owns k%32.
// Dynamic smem: max(16*1024, 512*33) floats = 67584 B -> request 69632.
// ---------------------------------------------------------------------------
extern __shared__ float s_dyn[];

__global__ __launch_bounds__(256, 1) void kB(const float* __restrict__ obj) {
    float* Ms = s_dyn;
    const int tid = threadIdx.x;

    // stage M (64 KB) in smem
    {
        float4*       d4 = reinterpret_cast<float4*>(Ms);
        const float4* s4 = reinterpret_cast<const float4*>(g_M);
        for (int i = tid; i < 4096; i += 256) d4[i] = s4[i];
    }
    __syncthreads();

    const int warp = tid >> 5, lane = tid & 31;
    const int row0 = blockIdx.x * 32 + warp * 4;
    const float4* objv = reinterpret_cast<const float4*>(obj);
    const float4* Ms4  = reinterpret_cast<const float4*>(Ms);

    ull acc[4][16];
    #pragma unroll
    for (int r = 0; r < 4; ++r)
        #pragma unroll
        for (int c = 0; c < 16; ++c) acc[r][c] = 0ull;   // bits 0 == {0.f,0.f}

    #pragma unroll
    for (int i = 0; i < 8; ++i) {
        const int k4 = lane + 32 * i;                    // float4 index, coalesced
        ull ovp[4][2];
        #pragma unroll
        for (int r = 0; r < 4; ++r) {
            float4 ov = objv[(row0 + r) * 256 + k4];
            ovp[r][0] = pk2(ov.x, ov.y);
            ovp[r][1] = pk2(ov.z, ov.w);
        }
        #pragma unroll
        for (int c = 0; c < 16; ++c) {
            float4 m = Ms4[c * 256 + k4];                // conflict-free LDS.128
            ull m0 = pk2(m.x, m.y), m1 = pk2(m.z, m.w);
            #pragma unroll
            for (int r = 0; r < 4; ++r) {
                acc[r][c] = ffma2(ovp[r][0], m0, acc[r][c]);
                acc[r][c] = ffma2(ovp[r][1], m1, acc[r][c]);
            }
        }
    }

    __syncthreads();   // everyone done reading Ms; reuse smem (stride-33 scratch)
    float* red = s_dyn;
    #pragma unroll
    for (int idx = 0; idx < 64; ++idx) {
        int r = idx >> 4, c = idx & 15;
        float lo, hi;
        asm("mov.b64 {%0, %1}, %2;" : "=f"(lo), "=f"(hi) : "l"(acc[r][c]));
        red[(warp * 64 + idx) * 33 + lane] = lo + hi;    // conflict-free STS
    }
    __syncthreads();

    // 512 outputs per block; stride-33 makes the 32-lane sum conflict-free
    for (int out = tid; out < 512; out += 256) {
        float s = 0.f;
        #pragma unroll
        for (int l = 0; l < 32; ++l) s += red[out * 33 + l];
        int c = out & 15;
        if (c >= 8) s += g_cvec[c - 8];                  // fold bias into obj half
        g_P[blockIdx.x * 512 + out] = s;                 // == g_P[row*16 + c16]
    }
}

// ---------------------------------------------------------------------------
// Kernel C: out[p][c] = P[sub][c] + P[obj][8+c]; also re-zero g_M for the
// next graph replay (kernel A accumulates with atomics from zero).
// Pairs read is format-adaptive (g_fmt) and index-masked (crash-proof).
// Grid: 256 x 256.
// ---------------------------------------------------------------------------
__global__ __launch_bounds__(256) void kC(const void* __restrict__ pairs,
                                          float* __restrict__ out) {
    const int p = blockIdx.x * 256 + threadIdx.x;

    int s, o;
    if (g_fmt) {                                          // int32 pairs
        int2 pr = reinterpret_cast<const int2*>(pairs)[p];
        s = pr.x; o = pr.y;
    } else {                                              // int64 pairs
        longlong2 pr = reinterpret_cast<const longlong2*>(pairs)[p];
        s = (int)pr.x; o = (int)pr.y;
    }
    s &= (N_OBJ - 1);                                     // no-op when valid
    o &= (N_OBJ - 1);

    const float4* P4 = reinterpret_cast<const float4*>(g_P);
    float4 a0 = P4[s * 4 + 0], a1 = P4[s * 4 + 1];
    float4 b0 = P4[o * 4 + 2], b1 = P4[o * 4 + 3];

    float4 r0 = make_float4(a0.x + b0.x, a0.y + b0.y, a0.z + b0.z, a0.w + b0.w);
    float4 r1 = make_float4(a1.x + b1.x, a1.y + b1.y, a1.z + b1.z, a1.w + b1.w);

    float4* o4 = reinterpret_cast<float4*>(out);
    o4[p * 2 + 0] = r0;
    o4[p * 2 + 1] = r1;

    if (p < 4096)   // 4096 float4 == 16384 floats == all of g_M
        reinterpret_cast<float4*>(g_M)[p] = make_float4(0.f, 0.f, 0.f, 0.f);
}

// ---------------------------------------------------------------------------
// Launch. Inputs bound BY ELEMENT COUNT (robust to metadata ordering):
//   obj_feats f32[4194304], pairs [131072 elems], W1 f32[2097152],
//   b1 f32[1024], W2 f32[8192], b2 f32[8].  Output: f32[524288].
// ---------------------------------------------------------------------------
extern "C" void kernel_launch(void* const* d_in, const int* in_sizes, int n_in,
                              void* d_out, int out_size) {
    (void)out_size;
    const float* obj   = nullptr;
    const void*  pairs = nullptr;
    const float* W1    = nullptr;
    const float* b1    = nullptr;
    const float* W2    = nullptr;
    const float* b2    = nullptr;

    for (int i = 0; i < n_in; ++i) {
        switch (in_sizes[i]) {
            case N_OBJ * OBJ_DIM:       obj   = (const float*)d_in[i]; break; // 4194304
            case N_PAIRS * 2:           pairs = d_in[i];               break; // 131072
            case OBJ_DIM * 2 * OBJ_DIM: W1    = (const float*)d_in[i]; break; // 2097152
            case OBJ_DIM:               b1    = (const float*)d_in[i]; break; // 1024
            case 8 * OBJ_DIM:           W2    = (const float*)d_in[i]; break; // 8192
            case 8:                     b2    = (const float*)d_in[i]; break; // 8
            default: break;
        }
    }
    float* out = (float*)d_out;

    // Idempotent, called every time (no static guards); not stream-ordered.
    cudaFuncSetAttribute(kB, cudaFuncAttributeMaxDynamicSharedMemorySize, 69632);

    // g_M starts zero (static zero-init on first call; kernel C re-zeros it
    // at the end of every run, keeping each graph replay identical).
    kDetect<<<1, 256>>>((const int*)pairs);
    kA<<<257, 256>>>(W1, W2, b1, b2);
    kB<<<128, 256, 69632>>>(obj);
    kC<<<256, 256>>>(pairs, out);
}

// round 11
// speedup vs baseline: 1.0012x; 1.0012x over previous
#include <cuda_runtime.h>
#include <cstdint>

typedef unsigned long long ull;

#define N_OBJ   4096
#define OBJ_DIM 1024
#define N_PAIRS 65536

// Scratch (device globals: no allocation allowed). 16B-aligned for float4 access.
// g_M layout: [c16][k], c16 in 0..15. c16<8: M[c][k] (sub half, k<1024 of W1 cols),
//             c16>=8: M[c-8][1024+k] (obj half).
__device__ __align__(16) float g_M[16 * 1024];   // 64 KB, ZERO before kernel A (atomics).
__device__ __align__(16) float g_cvec[8];        // W2@b1 + b2
__device__ __align__(16) float g_P[N_OBJ * 16];  // per-object projections (obj half + cvec)
__device__ int g_fmt;                            // 1 = pairs stored as int32, 0 = int64

// ---------------------------------------------------------------------------
// packed f32x2 helpers (Blackwell FFMA2 path)
// ---------------------------------------------------------------------------
__device__ __forceinline__ ull ffma2(ull a, ull b, ull c) {
    ull d;
    asm("fma.rn.f32x2 %0, %1, %2, %3;" : "=l"(d) : "l"(a), "l"(b), "l"(c));
    return d;
}
__device__ __forceinline__ ull pk2(float lo, float hi) {
    ull r;
    asm("mov.b64 %0, {%1, %2};" : "=l"(r) : "f"(lo), "f"(hi));
    return r;
}

// ---------------------------------------------------------------------------
// kDetect: decide pairs dtype. Read only the first 131072 int32 words (valid
// under BOTH hypotheses: int32 buffer = 131072 ints; int64 buffer = 262144).
// Under int64, odd words are high halves of indices < 4096 -> all zero.
// Under int32, odd words are 65536 random obj indices -> OR is nonzero.
// Deterministic: pure function of the input buffer.
// ---------------------------------------------------------------------------
__global__ __launch_bounds__(256) void kDetect(const int* __restrict__ pairs_i32) {
    __shared__ int s_or;
    if (threadIdx.x == 0) s_or = 0;
    __syncthreads();
    int v = 0;
    for (int i = threadIdx.x * 2 + 1; i < 131072; i += 512)
        v |= pairs_i32[i];
    #pragma unroll
    for (int o = 16; o; o >>= 1) v |= __shfl_xor_sync(0xffffffffu, v, o);
    if ((threadIdx.x & 31) == 0) atomicOr(&s_or, v);
    __syncthreads();
    if (threadIdx.x == 0) g_fmt = (s_or != 0) ? 1 : 0;
}

// ---------------------------------------------------------------------------
// Kernel A: g_M[c16][k] += partial of (W2 @ W1);  block 256 computes cvec.
// Grid: 257 blocks x 256 threads.
//   blocks 0..255: (kt = b & 63) k-tile of 32 columns, (jt = b >> 6) j-tile of 256.
// ---------------------------------------------------------------------------
__global__ __launch_bounds__(256) void kA(const float* __restrict__ W1,
                                          const float* __restrict__ W2,
                                          const float* __restrict__ b1,
                                          const float* __restrict__ b2) {
    __shared__ float sm[2048];   // phase1: W2 slice [8][256]; phase2: jy-reduction
    const int tid = threadIdx.x;

    if (blockIdx.x == 256) {     // cvec block
        int c = tid >> 5, lane = tid & 31;
        float s = 0.f;
        for (int j = lane; j < OBJ_DIM; j += 32)
            s += W2[c * OBJ_DIM + j] * b1[j];
        #pragma unroll
        for (int o = 16; o; o >>= 1) s += __shfl_xor_sync(0xffffffffu, s, o);
        if (lane == 0) g_cvec[c] = s + b2[c];
        return;
    }

    const int kt = blockIdx.x & 63;
    const int jt = blockIdx.x >> 6;    // 0..3
    const int kx = tid & 31;           // lane -> consecutive k (coalesced W1 reads)
    const int jy = tid >> 5;           // 0..7, constant per warp
    const int kk = kt * 32 + kx;       // 0..2047
    const int jb = jt * 256;

    // stage W2[c][jb..jb+256)
    for (int i = tid; i < 2048; i += 256)
        sm[i] = W2[(i >> 8) * OBJ_DIM + jb + (i & 255)];
    __syncthreads();

    float acc[8] = {0.f, 0.f, 0.f, 0.f, 0.f, 0.f, 0.f, 0.f};

    #pragma unroll
    for (int i = 0; i < 8; ++i) {
        float w[4];
        #pragma unroll
        for (int u = 0; u < 4; ++u) {               // batch loads for MLP
            int j = jy + 8 * (4 * i + u);           // local j in [0,256)
            w[u] = W1[(jb + j) * 2048 + kk];
        }
        #pragma unroll
        for (int u = 0; u < 4; ++u) {
            int j = jy + 8 * (4 * i + u);
            #pragma unroll
            for (int c = 0; c < 8; ++c)
                acc[c] += sm[c * 256 + j] * w[u];   // smem broadcast (j uniform/warp)
        }
    }

    __syncthreads();   // all warps done with W2 slice; reuse sm as reduction scratch
    #pragma unroll
    for (int c = 0; c < 8; ++c)
        sm[jy * 256 + kx * 8 + c] = acc[c];
    __syncthreads();

    // reduce over the 8 jy groups, then one atomicAdd per (k, c)
    {
        int kx2 = tid >> 3, c = tid & 7;
        float s = 0.f;
        #pragma unroll
        for (int q = 0; q < 8; ++q) s += sm[q * 256 + kx2 * 8 + c];
        int kk2 = kt * 32 + kx2;
        int c16 = ((kk2 >> 10) << 3) + c;
        atomicAdd(&g_M[c16 * 1024 + (kk2 & 1023)], s);
    }
}

// ---------------------------------------------------------------------------
// Kernel B: P[row][c16] = obj_feats[row] . Ms[c16]   (+ cvec on obj half)
// Grid: 128 blocks x 256 threads (8 warps). Warp owns 4 rows; lane owns k%32.
// Dynamic smem: max(16*1024, 512*33) floats = 67584 B -> request 69632.
// ---------------------------------------------------------------------------
extern __shared__ float s_dyn[];

__global__ __launch_bounds__(256, 1) void kB(const float* __restrict__ obj) {
    float* Ms = s_dyn;
    const int tid = threadIdx.x;

    // stage M (64 KB) in smem
    {
        float4*       d4 = reinterpret_cast<float4*>(Ms);
        const float4* s4 = reinterpret_cast<const float4*>(g_M);
        for (int i = tid; i < 4096; i += 256) d4[i] = s4[i];
    }
    __syncthreads();

    const int warp = tid >> 5, lane = tid & 31;
    const int row0 = blockIdx.x * 32 + warp * 4;
    const float4* objv = reinterpret_cast<const float4*>(obj);
    const float4* Ms4  = reinterpret_cast<const float4*>(Ms);

    ull acc[4][16];
    #pragma unroll
    for (int r = 0; r < 4; ++r)
        #pragma unroll
        for (int c = 0; c < 16; ++c) acc[r][c] = 0ull;   // bits 0 == {0.f,0.f}

    #pragma unroll
    for (int i = 0; i < 8; ++i) {
        const int k4 = lane + 32 * i;                    // float4 index, coalesced
        ull ovp[4][2];
        #pragma unroll
        for (int r = 0; r < 4; ++r) {
            float4 ov = objv[(row0 + r) * 256 + k4];
            ovp[r][0] = pk2(ov.x, ov.y);
            ovp[r][1] = pk2(ov.z, ov.w);
        }
        #pragma unroll
        for (int c = 0; c < 16; ++c) {
            float4 m = Ms4[c * 256 + k4];                // conflict-free LDS.128
            ull m0 = pk2(m.x, m.y), m1 = pk2(m.z, m.w);
            #pragma unroll
            for (int r = 0; r < 4; ++r) {
                acc[r][c] = ffma2(ovp[r][0], m0, acc[r][c]);
                acc[r][c] = ffma2(ovp[r][1], m1, acc[r][c]);
            }
        }
    }

    __syncthreads();   // everyone done reading Ms; reuse smem (stride-33 scratch)
    float* red = s_dyn;
    #pragma unroll
    for (int idx = 0; idx < 64; ++idx) {
        int r = idx >> 4, c = idx & 15;
        float lo, hi;
        asm("mov.b64 {%0, %1}, %2;" : "=f"(lo), "=f"(hi) : "l"(acc[r][c]));
        red[(warp * 64 + idx) * 33 + lane] = lo + hi;    // conflict-free STS
    }
    __syncthreads();

    // 512 outputs per block; stride-33 makes the 32-lane sum conflict-free
    for (int out = tid; out < 512; out += 256) {
        float s = 0.f;
        #pragma unroll
        for (int l = 0; l < 32; ++l) s += red[out * 33 + l];
        int c = out & 15;
        if (c >= 8) s += g_cvec[c - 8];                  // fold bias into obj half
        g_P[blockIdx.x * 512 + out] = s;                 // == g_P[row*16 + c16]
    }
}

// ---------------------------------------------------------------------------
// Kernel C: out[p][c] = P[sub][c] + P[obj][8+c]; also re-zero g_M for the
// next graph replay (kernel A accumulates with atomics from zero).
// Pairs read is format-adaptive (g_fmt) and index-masked (crash-proof).
// Grid: 256 x 256.
// ---------------------------------------------------------------------------
__global__ __launch_bounds__(256) void kC(const void* __restrict__ pairs,
                                          float* __restrict__ out) {
    const int p = blockIdx.x * 256 + threadIdx.x;

    int s, o;
    if (g_fmt) {                                          // int32 pairs
        int2 pr = reinterpret_cast<const int2*>(pairs)[p];
        s = pr.x; o = pr.y;
    } else {                                              // int64 pairs
        longlong2 pr = reinterpret_cast<const longlong2*>(pairs)[p];
        s = (int)pr.x; o = (int)pr.y;
    }
    s &= (N_OBJ - 1);                                     // no-op when valid
    o &= (N_OBJ - 1);

    const float4* P4 = reinterpret_cast<const float4*>(g_P);
    float4 a0 = P4[s * 4 + 0], a1 = P4[s * 4 + 1];
    float4 b0 = P4[o * 4 + 2], b1 = P4[o * 4 + 3];

    float4 r0 = make_float4(a0.x + b0.x, a0.y + b0.y, a0.z + b0.z, a0.w + b0.w);
    float4 r1 = make_float4(a1.x + b1.x, a1.y + b1.y, a1.z + b1.z, a1.w + b1.w);

    float4* o4 = reinterpret_cast<float4*>(out);
    o4[p * 2 + 0] = r0;
    o4[p * 2 + 1] = r1;

    if (p < 4096)   // 4096 float4 == 16384 floats == all of g_M
        reinterpret_cast<float4*>(g_M)[p] = make_float4(0.f, 0.f, 0.f, 0.f);
}

// ---------------------------------------------------------------------------
// Launch. Inputs bound BY ELEMENT COUNT (robust to metadata ordering):
//   obj_feats f32[4194304], pairs [131072 elems], W1 f32[2097152],
//   b1 f32[1024], W2 f32[8192], b2 f32[8].  Output: f32[524288].
// ---------------------------------------------------------------------------
extern "C" void kernel_launch(void* const* d_in, const int* in_sizes, int n_in,
                              void* d_out, int out_size) {
    (void)out_size;
    const float* obj   = nullptr;
    const void*  pairs = nullptr;
    const float* W1    = nullptr;
    const float* b1    = nullptr;
    const float* W2    = nullptr;
    const float* b2    = nullptr;

    for (int i = 0; i < n_in; ++i) {
        switch (in_sizes[i]) {
            case N_OBJ * OBJ_DIM:       obj   = (const float*)d_in[i]; break; // 4194304
            case N_PAIRS * 2:           pairs = d_in[i];               break; // 131072
            case OBJ_DIM * 2 * OBJ_DIM: W1    = (const float*)d_in[i]; break; // 2097152
            case OBJ_DIM:               b1    = (const float*)d_in[i]; break; // 1024
            case 8 * OBJ_DIM:           W2    = (const float*)d_in[i]; break; // 8192
            case 8:                     b2    = (const float*)d_in[i]; break; // 8
            default: break;
        }
    }
    float* out = (float*)d_out;

    // Idempotent, called every time (no static guards); not stream-ordered.
    cudaFuncSetAttribute(kB, cudaFuncAttributeMaxDynamicSharedMemorySize, 69632);

    // g_M starts zero (static zero-init on first call; kernel C re-zeros it
    // at the end of every run, keeping each graph replay identical).
    kDetect<<<1, 256>>>((const int*)pairs);
    kA<<<257, 256>>>(W1, W2, b1, b2);
    kB<<<128, 256, 69632>>>(obj);
    kC<<<256, 256>>>(pairs, out);
}